// round 10
// baseline (speedup 1.0000x reference)
#include <cuda_runtime.h>

// PCEN stack, round 9: eliminate the forward pass-2 loop + smem Mpart slab.
//
// Key identity set (exact, incl. scipy filtfilt boundaries; validated R7/R8):
//   forward:  A[t] = x[t] + q*A[t-1],  A[-1] = x[0]/s
//   backward: G[t] = x[t] + q*G[t+1],  G[T]  = A[T-1]
//   filtfilt: z[t] = s/(2-s) * (A[t] + G[t] - x[t])
//
// New this round: A's chunk-end value comes directly from the warp scan
// (A_end = Escan + Q16^(lane+1) * H), and A[i] inside the chunk is
// reconstructed DESCENDING via the inverse recurrence A[i-1] = (A[i]-x[i])/q
// inside the single final loop. No second forward loop, no Mpart storage,
// no forward carry. Worst-case inverse amplification (k3: (1/0.75)^16 ~ 99x
// on ~2e-7 abs error, weight 0.036) adds ~2e-6 to M — well under tolerance.
//
// Epilogue identities (validated ~1.1e-6):
//   log(EPS)+log1p(M/EPS) = log(M+EPS)
//   M'/delta = exp2(-alpha*lg2(M+EPS) - ld*log2e)
//   (x*M+d)^r - d^r = d^r*(exp2(r*lg2(1 + x*M'/d)) - 1)

static __device__ __forceinline__ float ex2_(float v) {
    float r; asm("ex2.approx.f32 %0, %1;" : "=f"(r) : "f"(v)); return r;
}
static __device__ __forceinline__ float lg2_(float v) {
    float r; asm("lg2.approx.f32 %0, %1;" : "=f"(r) : "f"(v)); return r;
}

static constexpr __host__ __device__ double dpow(double b, int n) {
    double r = 1.0;
    for (int i = 0; i < n; ++i) r *= b;
    return r;
}
static constexpr __host__ __device__ float cpf(double v) {
    return (v < 1.0e-37 && v > -1.0e-37) ? 0.0f : (float)v;
}

static constexpr float s0 = 0.015f, s1 = 0.04f, s2 = 0.1f, s3 = 0.25f;
static constexpr float q0 = 1.f - s0, q1 = 1.f - s1, q2 = 1.f - s2, q3 = 1.f - s3;
static constexpr float iq0 = 1.f / q0, iq1 = 1.f / q1, iq2 = 1.f / q2, iq3 = 1.f / q3;
static constexpr float P16_0  = cpf(dpow(q0, 16)),  P16_1  = cpf(dpow(q1, 16)),
                       P16_2  = cpf(dpow(q2, 16)),  P16_3  = cpf(dpow(q3, 16));
static constexpr float P32_0  = cpf(dpow(q0, 32)),  P32_1  = cpf(dpow(q1, 32)),
                       P32_2  = cpf(dpow(q2, 32)),  P32_3  = cpf(dpow(q3, 32));
static constexpr float P64_0  = cpf(dpow(q0, 64)),  P64_1  = cpf(dpow(q1, 64)),
                       P64_2  = cpf(dpow(q2, 64));
static constexpr float P128_0 = cpf(dpow(q0, 128)), P128_1 = cpf(dpow(q1, 128));
static constexpr float P256_0 = cpf(dpow(q0, 256));
static constexpr float P512_0 = cpf(dpow(q0, 512)), P512_1 = cpf(dpow(q1, 512)),
                       P512_2 = cpf(dpow(q2, 512)), P512_3 = cpf(dpow(q3, 512));

__global__ __launch_bounds__(128, 8)
void pcen_kernel(const float* __restrict__ x,
                 const float* __restrict__ i_sig_alpha,
                 const float* __restrict__ log_delta,
                 const float* __restrict__ i_sig_r,
                 const float* __restrict__ z_ks,
                 float* __restrict__ out,
                 int P, int F)
{
    constexpr int T = 2048, CH = 16, K = 4, NW = 4;
    constexpr unsigned ALL = 0xffffffffu;

    const int row  = blockIdx.x;                 // ((b*P)+p)*F + f
    const int p    = (row / F) % P;
    const int f    = row % F;
    const int base = row * T;
    const int tid  = threadIdx.x;
    const int lane = tid & 31;
    const int w    = tid >> 5;

    // fwd lane power Q16^(lane+1) (for A_end), bwd lane power Q16^(31-lane)
    const float lf = (float)(lane + 1), lb = (float)(31 - lane);
    const float g0 = lg2_(P16_0), g1 = lg2_(P16_1), g2 = lg2_(P16_2), g3 = lg2_(P16_3);
    const float Qlf0 = ex2_(lf * g0), Qlf1 = ex2_(lf * g1),
                Qlf2 = ex2_(lf * g2), Qlf3 = ex2_(lf * g3);
    const float Qlb0 = ex2_(lb * g0), Qlb1 = ex2_(lb * g1),
                Qlb2 = ex2_(lb * g2), Qlb3 = ex2_(lb * g3);

    // ---- per-(p,f) scalars ----
    const float alpha  = 1.0f / (1.0f + __expf(-i_sig_alpha[p]));
    const float rr     = 1.0f / (1.0f + __expf(-i_sig_r[p]));
    const float ld     = log_delta[p];
    const float nalpha = -alpha;
    const float c2     = -ld * 1.4426950408889634f;            // -ld*log2e
    const float dr     = ex2_(rr * ld * 1.4426950408889634f);  // delta^r

    float zk0 = z_ks[(p * K + 0) * F + f];
    float zk1 = z_ks[(p * K + 1) * F + f];
    float zk2 = z_ks[(p * K + 2) * F + f];
    float zk3 = z_ks[(p * K + 3) * F + f];
    float zm = fmaxf(fmaxf(zk0, zk1), fmaxf(zk2, zk3));
    float e0 = __expf(zk0 - zm), e1 = __expf(zk1 - zm),
          e2 = __expf(zk2 - zm), e3 = __expf(zk3 - zm);
    const float inv_sum = 1.0f / (e0 + e1 + e2 + e3);
    // wc_k = softmax_k * s_k/(2-s_k)   (z_k = s/(2-s) * (A+G-x))
    const float wc0 = e0 * inv_sum * (s0 / (2.f - s0));
    const float wc1 = e1 * inv_sum * (s1 / (2.f - s1));
    const float wc2 = e2 * inv_sum * (s2 / (2.f - s2));
    const float wc3 = e3 * inv_sum * (s3 / (2.f - s3));
    const float nwcx = -(wc0 + wc1 + wc2 + wc3);   // coefficient of -x[t]

    // ---- load x: 16 contiguous floats (4x LDG.128) ----
    float xr[CH];
    const float4* xv = reinterpret_cast<const float4*>(x + base + tid * CH);
#pragma unroll
    for (int j = 0; j < CH / 4; ++j) {
        float4 v = xv[j];
        xr[4*j+0] = v.x; xr[4*j+1] = v.y; xr[4*j+2] = v.z; xr[4*j+3] = v.w;
    }

    __shared__ float smA[NW][K];   // forward warp aggregates
    __shared__ float smB[NW][K];   // backward warp aggregates
    __shared__ float smInit[K];    // backward virtual init = A[T-1]
    __shared__ float smX0;         // x[0]

    // ===== fused pass1: fwd + bwd zero-init chunk sums on x (8-way ILP) =====
    float E0 = 0.f, E1 = 0.f, E2 = 0.f, E3 = 0.f;   // fwd: ends at chunk last elem
    float B0 = 0.f, B1 = 0.f, B2 = 0.f, B3 = 0.f;   // bwd: ends at chunk first elem
#pragma unroll
    for (int i = 0; i < CH; ++i) {
        float xa = xr[i], xb = xr[CH - 1 - i];
        E0 = fmaf(q0, E0, xa);
        E1 = fmaf(q1, E1, xa);
        E2 = fmaf(q2, E2, xa);
        E3 = fmaf(q3, E3, xa);
        B0 = fmaf(q0, B0, xb);
        B1 = fmaf(q1, B1, xb);
        B2 = fmaf(q2, B2, xb);
        B3 = fmaf(q3, B3, xb);
    }

    // ===== warp scans; per-k truncation (factor<1e-8 dropped): 5/4/3/2 steps =====
    {
        float v;
        v = __shfl_up_sync(ALL, E0, 1);  if (lane >= 1)  E0 = fmaf(P16_0, v, E0);
        v = __shfl_up_sync(ALL, E0, 2);  if (lane >= 2)  E0 = fmaf(P32_0, v, E0);
        v = __shfl_up_sync(ALL, E0, 4);  if (lane >= 4)  E0 = fmaf(P64_0, v, E0);
        v = __shfl_up_sync(ALL, E0, 8);  if (lane >= 8)  E0 = fmaf(P128_0, v, E0);
        v = __shfl_up_sync(ALL, E0, 16); if (lane >= 16) E0 = fmaf(P256_0, v, E0);
        v = __shfl_up_sync(ALL, E1, 1);  if (lane >= 1)  E1 = fmaf(P16_1, v, E1);
        v = __shfl_up_sync(ALL, E1, 2);  if (lane >= 2)  E1 = fmaf(P32_1, v, E1);
        v = __shfl_up_sync(ALL, E1, 4);  if (lane >= 4)  E1 = fmaf(P64_1, v, E1);
        v = __shfl_up_sync(ALL, E1, 8);  if (lane >= 8)  E1 = fmaf(P128_1, v, E1);
        v = __shfl_up_sync(ALL, E2, 1);  if (lane >= 1)  E2 = fmaf(P16_2, v, E2);
        v = __shfl_up_sync(ALL, E2, 2);  if (lane >= 2)  E2 = fmaf(P32_2, v, E2);
        v = __shfl_up_sync(ALL, E2, 4);  if (lane >= 4)  E2 = fmaf(P64_2, v, E2);
        v = __shfl_up_sync(ALL, E3, 1);  if (lane >= 1)  E3 = fmaf(P16_3, v, E3);
        v = __shfl_up_sync(ALL, E3, 2);  if (lane >= 2)  E3 = fmaf(P32_3, v, E3);

        v = __shfl_down_sync(ALL, B0, 1);  if (lane < 31) B0 = fmaf(P16_0, v, B0);
        v = __shfl_down_sync(ALL, B0, 2);  if (lane < 30) B0 = fmaf(P32_0, v, B0);
        v = __shfl_down_sync(ALL, B0, 4);  if (lane < 28) B0 = fmaf(P64_0, v, B0);
        v = __shfl_down_sync(ALL, B0, 8);  if (lane < 24) B0 = fmaf(P128_0, v, B0);
        v = __shfl_down_sync(ALL, B0, 16); if (lane < 16) B0 = fmaf(P256_0, v, B0);
        v = __shfl_down_sync(ALL, B1, 1);  if (lane < 31) B1 = fmaf(P16_1, v, B1);
        v = __shfl_down_sync(ALL, B1, 2);  if (lane < 30) B1 = fmaf(P32_1, v, B1);
        v = __shfl_down_sync(ALL, B1, 4);  if (lane < 28) B1 = fmaf(P64_1, v, B1);
        v = __shfl_down_sync(ALL, B1, 8);  if (lane < 24) B1 = fmaf(P128_1, v, B1);
        v = __shfl_down_sync(ALL, B2, 1);  if (lane < 31) B2 = fmaf(P16_2, v, B2);
        v = __shfl_down_sync(ALL, B2, 2);  if (lane < 30) B2 = fmaf(P32_2, v, B2);
        v = __shfl_down_sync(ALL, B2, 4);  if (lane < 28) B2 = fmaf(P64_2, v, B2);
        v = __shfl_down_sync(ALL, B3, 1);  if (lane < 31) B3 = fmaf(P16_3, v, B3);
        v = __shfl_down_sync(ALL, B3, 2);  if (lane < 30) B3 = fmaf(P32_3, v, B3);
    }

    if (lane == 31) { smA[w][0] = E0; smA[w][1] = E1; smA[w][2] = E2; smA[w][3] = E3; }
    if (lane == 0)  { smB[w][0] = B0; smB[w][1] = B1; smB[w][2] = B2; smB[w][3] = B3; }
    if (tid == 0)   smX0 = xr[0];
    __syncthreads();

    // ===== A at own chunk end: A_end = Escan + Q16^(lane+1) * H_w =====
    float ae0, ae1, ae2, ae3;
    {
        const float x0s = smX0;
        float H0 = x0s * (1.f / s0), H1 = x0s * (1.f / s1);   // seed A[-1] = x0/s
        float H2 = x0s * (1.f / s2), H3 = x0s * (1.f / s3);
#pragma unroll
        for (int j = 0; j < NW - 1; ++j) {
            if (j < w) {
                H0 = fmaf(P512_0, H0, smA[j][0]);
                H1 = fmaf(P512_1, H1, smA[j][1]);
                H2 = fmaf(P512_2, H2, smA[j][2]);
                H3 = fmaf(P512_3, H3, smA[j][3]);
            }
        }
        ae0 = fmaf(Qlf0, H0, E0);
        ae1 = fmaf(Qlf1, H1, E1);
        ae2 = fmaf(Qlf2, H2, E2);
        ae3 = fmaf(Qlf3, H3, E3);
    }
    if (tid == T / CH - 1) {              // A[T-1] -> backward virtual init
        smInit[0] = ae0; smInit[1] = ae1; smInit[2] = ae2; smInit[3] = ae3;
    }
    __syncthreads();

    // ===== backward carries: cb = Q16^(31-lane) * Hb_w + Bscan[lane+1] =====
    float cb0, cb1, cb2, cb3;
    {
        float v0 = __shfl_down_sync(ALL, B0, 1);
        float v1 = __shfl_down_sync(ALL, B1, 1);
        float v2 = __shfl_down_sync(ALL, B2, 1);
        float v3 = __shfl_down_sync(ALL, B3, 1);
        float sx0 = (lane < 31) ? v0 : 0.f, sx1 = (lane < 31) ? v1 : 0.f;
        float sx2 = (lane < 31) ? v2 : 0.f, sx3 = (lane < 31) ? v3 : 0.f;
        float H0 = smInit[0], H1 = smInit[1], H2 = smInit[2], H3 = smInit[3];
#pragma unroll
        for (int j = NW - 1; j >= 1; --j) {
            if (j > w) {
                H0 = fmaf(P512_0, H0, smB[j][0]);
                H1 = fmaf(P512_1, H1, smB[j][1]);
                H2 = fmaf(P512_2, H2, smB[j][2]);
                H3 = fmaf(P512_3, H3, smB[j][3]);
            }
        }
        cb0 = fmaf(Qlb0, H0, sx0);
        cb1 = fmaf(Qlb1, H1, sx1);
        cb2 = fmaf(Qlb2, H2, sx2);
        cb3 = fmaf(Qlb3, H3, sx3);
    }

    // ===== single final loop (descending): G fwd-chain, A inverse-chain,
    //       mix + PCEN epilogue + float4 stores =====
    {
        float gg0 = cb0, gg1 = cb1, gg2 = cb2, gg3 = cb3;
        float a0 = ae0, a1 = ae1, a2 = ae2, a3 = ae3;    // A at i = CH-1
        float* outp = out + base + tid * CH;
#pragma unroll
        for (int jg = CH / 4 - 1; jg >= 0; --jg) {
            float o0, o1, o2, o3;
#pragma unroll
            for (int ii = 3; ii >= 0; --ii) {
                const int i = 4 * jg + ii;
                const float xi = xr[i];
                gg0 = fmaf(q0, gg0, xi);
                gg1 = fmaf(q1, gg1, xi);
                gg2 = fmaf(q2, gg2, xi);
                gg3 = fmaf(q3, gg3, xi);
                float t0 = a0 + gg0, t1 = a1 + gg1;
                float t2 = a2 + gg2, t3 = a3 + gg3;
                float M = fmaf(nwcx, xi, 1e-6f);
                M = fmaf(wc0, t0, M);
                M = fmaf(wc1, t1, M);
                M = fmaf(wc2, t2, M);
                M = fmaf(wc3, t3, M);
                float Mp = ex2_(fmaf(nalpha, lg2_(M), c2));   // (M+eps)^(-a)/delta
                float u  = fmaf(xi, Mp, 1.0f);
                float o  = fmaf(dr, ex2_(rr * lg2_(u)), -dr);
                // step A backward: A[i-1] = (A[i] - x[i]) / q
                a0 = (a0 - xi) * iq0;
                a1 = (a1 - xi) * iq1;
                a2 = (a2 - xi) * iq2;
                a3 = (a3 - xi) * iq3;
                if (ii == 0) o0 = o; else if (ii == 1) o1 = o;
                else if (ii == 2) o2 = o; else o3 = o;
            }
            reinterpret_cast<float4*>(outp)[jg] = make_float4(o0, o1, o2, o3);
        }
    }
}

extern "C" void kernel_launch(void* const* d_in, const int* in_sizes, int n_in,
                              void* d_out, int out_size)
{
    const float* x   = (const float*)d_in[0];
    const float* isa = (const float*)d_in[1];
    const float* ldl = (const float*)d_in[2];
    const float* isr = (const float*)d_in[3];
    const float* zks = (const float*)d_in[4];
    float* out = (float*)d_out;

    const int P    = in_sizes[1];                 // 4
    const int F    = in_sizes[4] / (P * 4);       // 128 (z_ks is [P,K,F], K=4)
    const int rows = in_sizes[0] / 2048;          // B*P*F = 8192

    pcen_kernel<<<rows, 128>>>(x, isa, ldl, isr, zks, out, P, F);
}

// round 11
// speedup vs baseline: 1.0442x; 1.0442x over previous
#include <cuda_runtime.h>

// PCEN stack, round 10: raise occupancy cap 8 -> 10 blocks/SM (50% -> 62.5%).
// R8/R9 showed the kernel is latency-exposure-bound at 32 warps/SM: instr
// count changes were neutral. Here the register peak (xr[16] held live
// end-to-end, 63 regs) is broken:
//   - xr dies after pass1+scans; the final loop RELOADS x via a 2-stage
//     float4 pipeline (L2-hit latency covered by the extra warps).
//   - all per-(p,f) scalar setup moved after the first __syncthreads.
//
// Algorithm (exact partial-fraction filtfilt, validated R7-R9):
//   forward:  A[t] = x[t] + q*A[t-1],  A[-1] = x[0]/s
//   backward: G[t] = x[t] + q*G[t+1],  G[T]  = A[T-1]
//   filtfilt: z[t] = s/(2-s) * (A[t] + G[t] - x[t])
// A_end per chunk comes from the warp scan; A[i] inside the chunk is
// reconstructed descending via A[i-1] = (A[i]-x[i])/q.
//
// Epilogue: M'/delta = exp2(-alpha*lg2(M+eps) - ld*log2e);
//           out = dr*(exp2(r*lg2(1 + x*M'/delta)) - 1).

static __device__ __forceinline__ float ex2_(float v) {
    float r; asm("ex2.approx.f32 %0, %1;" : "=f"(r) : "f"(v)); return r;
}
static __device__ __forceinline__ float lg2_(float v) {
    float r; asm("lg2.approx.f32 %0, %1;" : "=f"(r) : "f"(v)); return r;
}

static constexpr __host__ __device__ double dpow(double b, int n) {
    double r = 1.0;
    for (int i = 0; i < n; ++i) r *= b;
    return r;
}
static constexpr __host__ __device__ float cpf(double v) {
    return (v < 1.0e-37 && v > -1.0e-37) ? 0.0f : (float)v;
}

static constexpr float s0 = 0.015f, s1 = 0.04f, s2 = 0.1f, s3 = 0.25f;
static constexpr float q0 = 1.f - s0, q1 = 1.f - s1, q2 = 1.f - s2, q3 = 1.f - s3;
static constexpr float iq0 = 1.f / q0, iq1 = 1.f / q1, iq2 = 1.f / q2, iq3 = 1.f / q3;
static constexpr float P16_0  = cpf(dpow(q0, 16)),  P16_1  = cpf(dpow(q1, 16)),
                       P16_2  = cpf(dpow(q2, 16)),  P16_3  = cpf(dpow(q3, 16));
static constexpr float P32_0  = cpf(dpow(q0, 32)),  P32_1  = cpf(dpow(q1, 32)),
                       P32_2  = cpf(dpow(q2, 32)),  P32_3  = cpf(dpow(q3, 32));
static constexpr float P64_0  = cpf(dpow(q0, 64)),  P64_1  = cpf(dpow(q1, 64)),
                       P64_2  = cpf(dpow(q2, 64));
static constexpr float P128_0 = cpf(dpow(q0, 128)), P128_1 = cpf(dpow(q1, 128));
static constexpr float P256_0 = cpf(dpow(q0, 256));
static constexpr float P512_0 = cpf(dpow(q0, 512)), P512_1 = cpf(dpow(q1, 512)),
                       P512_2 = cpf(dpow(q2, 512)), P512_3 = cpf(dpow(q3, 512));

__global__ __launch_bounds__(128, 10)
void pcen_kernel(const float* __restrict__ x,
                 const float* __restrict__ i_sig_alpha,
                 const float* __restrict__ log_delta,
                 const float* __restrict__ i_sig_r,
                 const float* __restrict__ z_ks,
                 float* __restrict__ out,
                 int P, int F)
{
    constexpr int T = 2048, CH = 16, K = 4, NW = 4;
    constexpr unsigned ALL = 0xffffffffu;

    const int row  = blockIdx.x;                 // ((b*P)+p)*F + f
    const int base = row * T;
    const int tid  = threadIdx.x;
    const int lane = tid & 31;
    const int w    = tid >> 5;

    __shared__ float smA[NW][K];   // forward warp aggregates
    __shared__ float smB[NW][K];   // backward warp aggregates
    __shared__ float smInit[K];    // backward virtual init = A[T-1]
    __shared__ float smX0;         // x[0]

    const float4* xv = reinterpret_cast<const float4*>(x + base + tid * CH);

    // ===== phase 1: load x, fused fwd+bwd zero-init chunk sums, warp scans =====
    float E0 = 0.f, E1 = 0.f, E2 = 0.f, E3 = 0.f;   // fwd: ends at chunk last elem
    float B0 = 0.f, B1 = 0.f, B2 = 0.f, B3 = 0.f;   // bwd: ends at chunk first elem
    {
        float xr[CH];
#pragma unroll
        for (int j = 0; j < CH / 4; ++j) {
            float4 v = xv[j];
            xr[4*j+0] = v.x; xr[4*j+1] = v.y; xr[4*j+2] = v.z; xr[4*j+3] = v.w;
        }
#pragma unroll
        for (int i = 0; i < CH; ++i) {
            float xa = xr[i], xb = xr[CH - 1 - i];
            E0 = fmaf(q0, E0, xa);
            E1 = fmaf(q1, E1, xa);
            E2 = fmaf(q2, E2, xa);
            E3 = fmaf(q3, E3, xa);
            B0 = fmaf(q0, B0, xb);
            B1 = fmaf(q1, B1, xb);
            B2 = fmaf(q2, B2, xb);
            B3 = fmaf(q3, B3, xb);
        }
        if (tid == 0) smX0 = xr[0];
    }   // xr dead here

    // warp scans; per-k truncation (dropped factors < ~3e-5): 5/4/3/2 steps
    {
        float v;
        v = __shfl_up_sync(ALL, E0, 1);  if (lane >= 1)  E0 = fmaf(P16_0, v, E0);
        v = __shfl_up_sync(ALL, E0, 2);  if (lane >= 2)  E0 = fmaf(P32_0, v, E0);
        v = __shfl_up_sync(ALL, E0, 4);  if (lane >= 4)  E0 = fmaf(P64_0, v, E0);
        v = __shfl_up_sync(ALL, E0, 8);  if (lane >= 8)  E0 = fmaf(P128_0, v, E0);
        v = __shfl_up_sync(ALL, E0, 16); if (lane >= 16) E0 = fmaf(P256_0, v, E0);
        v = __shfl_up_sync(ALL, E1, 1);  if (lane >= 1)  E1 = fmaf(P16_1, v, E1);
        v = __shfl_up_sync(ALL, E1, 2);  if (lane >= 2)  E1 = fmaf(P32_1, v, E1);
        v = __shfl_up_sync(ALL, E1, 4);  if (lane >= 4)  E1 = fmaf(P64_1, v, E1);
        v = __shfl_up_sync(ALL, E1, 8);  if (lane >= 8)  E1 = fmaf(P128_1, v, E1);
        v = __shfl_up_sync(ALL, E2, 1);  if (lane >= 1)  E2 = fmaf(P16_2, v, E2);
        v = __shfl_up_sync(ALL, E2, 2);  if (lane >= 2)  E2 = fmaf(P32_2, v, E2);
        v = __shfl_up_sync(ALL, E2, 4);  if (lane >= 4)  E2 = fmaf(P64_2, v, E2);
        v = __shfl_up_sync(ALL, E3, 1);  if (lane >= 1)  E3 = fmaf(P16_3, v, E3);
        v = __shfl_up_sync(ALL, E3, 2);  if (lane >= 2)  E3 = fmaf(P32_3, v, E3);

        v = __shfl_down_sync(ALL, B0, 1);  if (lane < 31) B0 = fmaf(P16_0, v, B0);
        v = __shfl_down_sync(ALL, B0, 2);  if (lane < 30) B0 = fmaf(P32_0, v, B0);
        v = __shfl_down_sync(ALL, B0, 4);  if (lane < 28) B0 = fmaf(P64_0, v, B0);
        v = __shfl_down_sync(ALL, B0, 8);  if (lane < 24) B0 = fmaf(P128_0, v, B0);
        v = __shfl_down_sync(ALL, B0, 16); if (lane < 16) B0 = fmaf(P256_0, v, B0);
        v = __shfl_down_sync(ALL, B1, 1);  if (lane < 31) B1 = fmaf(P16_1, v, B1);
        v = __shfl_down_sync(ALL, B1, 2);  if (lane < 30) B1 = fmaf(P32_1, v, B1);
        v = __shfl_down_sync(ALL, B1, 4);  if (lane < 28) B1 = fmaf(P64_1, v, B1);
        v = __shfl_down_sync(ALL, B1, 8);  if (lane < 24) B1 = fmaf(P128_1, v, B1);
        v = __shfl_down_sync(ALL, B2, 1);  if (lane < 31) B2 = fmaf(P16_2, v, B2);
        v = __shfl_down_sync(ALL, B2, 2);  if (lane < 30) B2 = fmaf(P32_2, v, B2);
        v = __shfl_down_sync(ALL, B2, 4);  if (lane < 28) B2 = fmaf(P64_2, v, B2);
        v = __shfl_down_sync(ALL, B3, 1);  if (lane < 31) B3 = fmaf(P16_3, v, B3);
        v = __shfl_down_sync(ALL, B3, 2);  if (lane < 30) B3 = fmaf(P32_3, v, B3);
    }

    if (lane == 31) { smA[w][0] = E0; smA[w][1] = E1; smA[w][2] = E2; smA[w][3] = E3; }
    if (lane == 0)  { smB[w][0] = B0; smB[w][1] = B1; smB[w][2] = B2; smB[w][3] = B3; }
    __syncthreads();

    // ===== phase 2: per-(p,f) scalars (overlaps with carry folds below) =====
    const int p = (row / F) % P;
    const int f = row % F;
    const float alpha  = 1.0f / (1.0f + __expf(-i_sig_alpha[p]));
    const float rr     = 1.0f / (1.0f + __expf(-i_sig_r[p]));
    const float ld     = log_delta[p];
    const float nalpha = -alpha;
    const float c2     = -ld * 1.4426950408889634f;            // -ld*log2e
    const float dr     = ex2_(rr * ld * 1.4426950408889634f);  // delta^r

    float zk0 = z_ks[(p * K + 0) * F + f];
    float zk1 = z_ks[(p * K + 1) * F + f];
    float zk2 = z_ks[(p * K + 2) * F + f];
    float zk3 = z_ks[(p * K + 3) * F + f];
    float zm = fmaxf(fmaxf(zk0, zk1), fmaxf(zk2, zk3));
    float e0 = __expf(zk0 - zm), e1 = __expf(zk1 - zm),
          e2 = __expf(zk2 - zm), e3 = __expf(zk3 - zm);
    const float inv_sum = 1.0f / (e0 + e1 + e2 + e3);
    const float wc0 = e0 * inv_sum * (s0 / (2.f - s0));
    const float wc1 = e1 * inv_sum * (s1 / (2.f - s1));
    const float wc2 = e2 * inv_sum * (s2 / (2.f - s2));
    const float wc3 = e3 * inv_sum * (s3 / (2.f - s3));
    const float nwcx = -(wc0 + wc1 + wc2 + wc3);   // coefficient of -x[t]

    // lane powers Q16^(lane+1) (fwd A_end) / Q16^(31-lane) (bwd carry)
    const float lf = (float)(lane + 1), lb = (float)(31 - lane);
    const float g0 = lg2_(P16_0), g1 = lg2_(P16_1), g2 = lg2_(P16_2), g3 = lg2_(P16_3);

    // ===== A at own chunk end: A_end = Escan + Q16^(lane+1) * H_w =====
    float ae0, ae1, ae2, ae3;
    {
        const float x0s = smX0;
        float H0 = x0s * (1.f / s0), H1 = x0s * (1.f / s1);   // seed A[-1] = x0/s
        float H2 = x0s * (1.f / s2), H3 = x0s * (1.f / s3);
#pragma unroll
        for (int j = 0; j < NW - 1; ++j) {
            if (j < w) {
                H0 = fmaf(P512_0, H0, smA[j][0]);
                H1 = fmaf(P512_1, H1, smA[j][1]);
                H2 = fmaf(P512_2, H2, smA[j][2]);
                H3 = fmaf(P512_3, H3, smA[j][3]);
            }
        }
        ae0 = fmaf(ex2_(lf * g0), H0, E0);
        ae1 = fmaf(ex2_(lf * g1), H1, E1);
        ae2 = fmaf(ex2_(lf * g2), H2, E2);
        ae3 = fmaf(ex2_(lf * g3), H3, E3);
    }
    if (tid == T / CH - 1) {              // A[T-1] -> backward virtual init
        smInit[0] = ae0; smInit[1] = ae1; smInit[2] = ae2; smInit[3] = ae3;
    }
    __syncthreads();

    // ===== backward carries: cb = Q16^(31-lane) * Hb_w + Bscan[lane+1] =====
    float cb0, cb1, cb2, cb3;
    {
        float v0 = __shfl_down_sync(ALL, B0, 1);
        float v1 = __shfl_down_sync(ALL, B1, 1);
        float v2 = __shfl_down_sync(ALL, B2, 1);
        float v3 = __shfl_down_sync(ALL, B3, 1);
        float sx0 = (lane < 31) ? v0 : 0.f, sx1 = (lane < 31) ? v1 : 0.f;
        float sx2 = (lane < 31) ? v2 : 0.f, sx3 = (lane < 31) ? v3 : 0.f;
        float H0 = smInit[0], H1 = smInit[1], H2 = smInit[2], H3 = smInit[3];
#pragma unroll
        for (int j = NW - 1; j >= 1; --j) {
            if (j > w) {
                H0 = fmaf(P512_0, H0, smB[j][0]);
                H1 = fmaf(P512_1, H1, smB[j][1]);
                H2 = fmaf(P512_2, H2, smB[j][2]);
                H3 = fmaf(P512_3, H3, smB[j][3]);
            }
        }
        cb0 = fmaf(ex2_(lb * g0), H0, sx0);
        cb1 = fmaf(ex2_(lb * g1), H1, sx1);
        cb2 = fmaf(ex2_(lb * g2), H2, sx2);
        cb3 = fmaf(ex2_(lb * g3), H3, sx3);
    }

    // ===== final loop (descending): reload x (2-stage pipeline), G fwd-chain,
    //       A inverse-chain, mix + PCEN epilogue + float4 stores =====
    {
        float gg0 = cb0, gg1 = cb1, gg2 = cb2, gg3 = cb3;
        float a0 = ae0, a1 = ae1, a2 = ae2, a3 = ae3;    // A at i = CH-1
        float* outp = out + base + tid * CH;
        float4 xc = xv[CH / 4 - 1];                      // preload last group
#pragma unroll
        for (int jg = CH / 4 - 1; jg >= 0; --jg) {
            float4 xn;
            if (jg > 0) xn = xv[jg - 1];                 // prefetch next group
            float xg[4] = { xc.x, xc.y, xc.z, xc.w };
            float o0, o1, o2, o3;
#pragma unroll
            for (int ii = 3; ii >= 0; --ii) {
                const float xi = xg[ii];
                gg0 = fmaf(q0, gg0, xi);
                gg1 = fmaf(q1, gg1, xi);
                gg2 = fmaf(q2, gg2, xi);
                gg3 = fmaf(q3, gg3, xi);
                float t0 = a0 + gg0, t1 = a1 + gg1;
                float t2 = a2 + gg2, t3 = a3 + gg3;
                float M = fmaf(nwcx, xi, 1e-6f);
                M = fmaf(wc0, t0, M);
                M = fmaf(wc1, t1, M);
                M = fmaf(wc2, t2, M);
                M = fmaf(wc3, t3, M);
                float Mp = ex2_(fmaf(nalpha, lg2_(M), c2));   // (M+eps)^(-a)/delta
                float u  = fmaf(xi, Mp, 1.0f);
                float o  = fmaf(dr, ex2_(rr * lg2_(u)), -dr);
                // step A backward: A[i-1] = (A[i] - x[i]) / q
                a0 = (a0 - xi) * iq0;
                a1 = (a1 - xi) * iq1;
                a2 = (a2 - xi) * iq2;
                a3 = (a3 - xi) * iq3;
                if (ii == 0) o0 = o; else if (ii == 1) o1 = o;
                else if (ii == 2) o2 = o; else o3 = o;
            }
            reinterpret_cast<float4*>(outp)[jg] = make_float4(o0, o1, o2, o3);
            xc = xn;
        }
    }
}

extern "C" void kernel_launch(void* const* d_in, const int* in_sizes, int n_in,
                              void* d_out, int out_size)
{
    const float* x   = (const float*)d_in[0];
    const float* isa = (const float*)d_in[1];
    const float* ldl = (const float*)d_in[2];
    const float* isr = (const float*)d_in[3];
    const float* zks = (const float*)d_in[4];
    float* out = (float*)d_out;

    const int P    = in_sizes[1];                 // 4
    const int F    = in_sizes[4] / (P * 4);       // 128 (z_ks is [P,K,F], K=4)
    const int rows = in_sizes[0] / 2048;          // B*P*F = 8192

    pcen_kernel<<<rows, 128>>>(x, isa, ldl, isr, zks, out, P, F);
}

// round 12
// speedup vs baseline: 1.0499x; 1.0055x over previous
#include <cuda_runtime.h>

// PCEN stack, round 11: ONE WARP PER ROW (CH=64) + coalesced smem staging.
//
// R10 post-mortem: 4 warps/row replicate ~500 warp-instrs of fixed cost, and
// the 64B-lane-stride LDG/STG pattern inflates L1 wavefronts 4x (16 lines per
// .128 access). This round: each warp owns a whole row (T=2048, 64 elems per
// lane). All global traffic is coalesced through a padded smem slab
// (word = e + (e>>6)*4 -> every access pattern used here is 4-phase = floor).
// Scans are warp-local (factor Q=q^64 truncates to 4/3/1/0 steps fwd+bwd),
// no __syncthreads, no cross-warp folds.
//
// Algorithm (exact partial-fraction filtfilt, validated R7-R10):
//   forward:  A[t] = x[t] + q*A[t-1],  A[-1] = x[0]/s
//   backward: G[t] = x[t] + q*G[t+1],  G[T]  = A[T-1]
//   filtfilt: z[t] = s/(2-s) * (A[t] + G[t] - x[t])
// Final loop runs DESCENDING: G by its natural chain; A by the inverse
// recurrence A[i-1] = (A[i]-x[i])/q. For k2/k3 (1/q)^64 would amplify error
// (up to 1e8), so zero-init chain checkpoints captured at i=15/31/47 in
// pass1 reseed a2/a3 every 16 elements (amplification <= 99, validated).
//
// Epilogue: M'/delta = exp2(-alpha*lg2(M+eps) - ld*log2e);
//           out = dr*(exp2(r*lg2(1 + x*M'/delta)) - 1).

static __device__ __forceinline__ float ex2_(float v) {
    float r; asm("ex2.approx.f32 %0, %1;" : "=f"(r) : "f"(v)); return r;
}
static __device__ __forceinline__ float lg2_(float v) {
    float r; asm("lg2.approx.f32 %0, %1;" : "=f"(r) : "f"(v)); return r;
}

static constexpr __host__ __device__ double dpow(double b, int n) {
    double r = 1.0;
    for (int i = 0; i < n; ++i) r *= b;
    return r;
}
static constexpr __host__ __device__ float cpf(double v) {
    return (v < 1.0e-37 && v > -1.0e-37) ? 0.0f : (float)v;
}

static constexpr float s0 = 0.015f, s1 = 0.04f, s2 = 0.1f, s3 = 0.25f;
static constexpr float q0 = 1.f - s0, q1 = 1.f - s1, q2 = 1.f - s2, q3 = 1.f - s3;
static constexpr float iq0 = 1.f / q0, iq1 = 1.f / q1, iq2 = 1.f / q2, iq3 = 1.f / q3;
static constexpr float is0 = 1.f / s0, is1 = 1.f / s1, is2 = 1.f / s2, is3 = 1.f / s3;
// warp-scan factors, Q = q^64 (chunk = 64 elems)
static constexpr float P64_0  = cpf(dpow(q0, 64)),  P64_1  = cpf(dpow(q1, 64)),
                       P64_2  = cpf(dpow(q2, 64)),  P64_3  = cpf(dpow(q3, 64));
static constexpr float P128_0 = cpf(dpow(q0, 128)), P128_1 = cpf(dpow(q1, 128));
static constexpr float P256_0 = cpf(dpow(q0, 256)), P256_1 = cpf(dpow(q1, 256));
static constexpr float P512_0 = cpf(dpow(q0, 512));
// intra-chunk checkpoint powers (reseed distance 16/32/48)
static constexpr float C16_2 = cpf(dpow(q2, 16)), C32_2 = cpf(dpow(q2, 32)),
                       C48_2 = cpf(dpow(q2, 48));
static constexpr float C16_3 = cpf(dpow(q3, 16)), C32_3 = cpf(dpow(q3, 32)),
                       C48_3 = cpf(dpow(q3, 48));

// padded smem slab: elem e -> word e + (e>>6)*4  (per-thread LDS.128 and all
// coalesced .128 patterns used here hit the 4-phase floor, 16B-aligned)
#define SMWORD(e) ((e) + (((e) >> 6) << 2))

__global__ __launch_bounds__(128, 6)
void pcen_kernel(const float* __restrict__ x,
                 const float* __restrict__ i_sig_alpha,
                 const float* __restrict__ log_delta,
                 const float* __restrict__ i_sig_r,
                 const float* __restrict__ z_ks,
                 float* __restrict__ out,
                 int P, int F)
{
    constexpr int T = 2048, K = 4;
    constexpr unsigned ALL = 0xffffffffu;
    constexpr int SLAB = 2176;     // 2048 + 32*4 pad words

    const int tid  = threadIdx.x;
    const int lane = tid & 31;
    const int w    = tid >> 5;
    const int row  = blockIdx.x * 4 + w;      // one warp per row
    const int base = row * T;

    __shared__ float sm[4][SLAB];
    float* smr = sm[w];

    // ---- early scalar loads (latency hidden behind staging/pass1) ----
    const int p = (row / F) % P;
    const int f = row % F;
    const float visa = i_sig_alpha[p];
    const float vld  = log_delta[p];
    const float visr = i_sig_r[p];
    const float zk0 = z_ks[(p * K + 0) * F + f];
    const float zk1 = z_ks[(p * K + 1) * F + f];
    const float zk2 = z_ks[(p * K + 2) * F + f];
    const float zk3 = z_ks[(p * K + 3) * F + f];

    // ---- stage-in: coalesced LDG.128 -> padded smem ----
    const float4* xg4 = reinterpret_cast<const float4*>(x + base);
#pragma unroll
    for (int it = 0; it < 16; ++it) {
        float4 v = xg4[it * 32 + lane];
        int e = it * 128 + lane * 4;
        *reinterpret_cast<float4*>(smr + SMWORD(e)) = v;
    }
    __syncwarp();

    const int wb = lane * 68;      // own-chunk word base (64 elems + 4 pad)

    // ---- pass1 fwd: zero-init E chains, checkpoints at i=15/31/47 ----
    float E0 = 0.f, E1 = 0.f, E2 = 0.f, E3 = 0.f;
    float eck2_0, eck2_1, eck2_2, eck3_0, eck3_1, eck3_2;
#pragma unroll
    for (int g = 0; g < 16; ++g) {
        float4 xv = *reinterpret_cast<const float4*>(smr + wb + g * 4);
        E0 = fmaf(q0, E0, xv.x); E1 = fmaf(q1, E1, xv.x);
        E2 = fmaf(q2, E2, xv.x); E3 = fmaf(q3, E3, xv.x);
        E0 = fmaf(q0, E0, xv.y); E1 = fmaf(q1, E1, xv.y);
        E2 = fmaf(q2, E2, xv.y); E3 = fmaf(q3, E3, xv.y);
        E0 = fmaf(q0, E0, xv.z); E1 = fmaf(q1, E1, xv.z);
        E2 = fmaf(q2, E2, xv.z); E3 = fmaf(q3, E3, xv.z);
        E0 = fmaf(q0, E0, xv.w); E1 = fmaf(q1, E1, xv.w);
        E2 = fmaf(q2, E2, xv.w); E3 = fmaf(q3, E3, xv.w);
        if (g == 3)  { eck2_0 = E2; eck3_0 = E3; }
        if (g == 7)  { eck2_1 = E2; eck3_1 = E3; }
        if (g == 11) { eck2_2 = E2; eck3_2 = E3; }
    }

    // ---- pass1 bwd: zero-init B chains (B = sum q^i x[start+i]) ----
    float B0 = 0.f, B1 = 0.f, B2 = 0.f, B3 = 0.f;
#pragma unroll
    for (int g = 15; g >= 0; --g) {
        float4 xv = *reinterpret_cast<const float4*>(smr + wb + g * 4);
        B0 = fmaf(q0, B0, xv.w); B1 = fmaf(q1, B1, xv.w);
        B2 = fmaf(q2, B2, xv.w); B3 = fmaf(q3, B3, xv.w);
        B0 = fmaf(q0, B0, xv.z); B1 = fmaf(q1, B1, xv.z);
        B2 = fmaf(q2, B2, xv.z); B3 = fmaf(q3, B3, xv.z);
        B0 = fmaf(q0, B0, xv.y); B1 = fmaf(q1, B1, xv.y);
        B2 = fmaf(q2, B2, xv.y); B3 = fmaf(q3, B3, xv.y);
        B0 = fmaf(q0, B0, xv.x); B1 = fmaf(q1, B1, xv.x);
        B2 = fmaf(q2, B2, xv.x); B3 = fmaf(q3, B3, xv.x);
    }

    // ---- warp scans; truncation by factor (<1e-7 dropped): 4/3/1/0 steps ----
    {
        float v;
        v = __shfl_up_sync(ALL, E0, 1); if (lane >= 1) E0 = fmaf(P64_0,  v, E0);
        v = __shfl_up_sync(ALL, E0, 2); if (lane >= 2) E0 = fmaf(P128_0, v, E0);
        v = __shfl_up_sync(ALL, E0, 4); if (lane >= 4) E0 = fmaf(P256_0, v, E0);
        v = __shfl_up_sync(ALL, E0, 8); if (lane >= 8) E0 = fmaf(P512_0, v, E0);
        v = __shfl_up_sync(ALL, E1, 1); if (lane >= 1) E1 = fmaf(P64_1,  v, E1);
        v = __shfl_up_sync(ALL, E1, 2); if (lane >= 2) E1 = fmaf(P128_1, v, E1);
        v = __shfl_up_sync(ALL, E1, 4); if (lane >= 4) E1 = fmaf(P256_1, v, E1);
        v = __shfl_up_sync(ALL, E2, 1); if (lane >= 1) E2 = fmaf(P64_2,  v, E2);

        v = __shfl_down_sync(ALL, B0, 1); if (lane < 31) B0 = fmaf(P64_0,  v, B0);
        v = __shfl_down_sync(ALL, B0, 2); if (lane < 30) B0 = fmaf(P128_0, v, B0);
        v = __shfl_down_sync(ALL, B0, 4); if (lane < 28) B0 = fmaf(P256_0, v, B0);
        v = __shfl_down_sync(ALL, B0, 8); if (lane < 24) B0 = fmaf(P512_0, v, B0);
        v = __shfl_down_sync(ALL, B1, 1); if (lane < 31) B1 = fmaf(P64_1,  v, B1);
        v = __shfl_down_sync(ALL, B1, 2); if (lane < 30) B1 = fmaf(P128_1, v, B1);
        v = __shfl_down_sync(ALL, B1, 4); if (lane < 28) B1 = fmaf(P256_1, v, B1);
        v = __shfl_down_sync(ALL, B2, 1); if (lane < 31) B2 = fmaf(P64_2,  v, B2);
    }

    // ---- per-(p,f) scalar math (loads already in flight) ----
    const float alpha  = 1.0f / (1.0f + __expf(-visa));
    const float rr     = 1.0f / (1.0f + __expf(-visr));
    const float nalpha = -alpha;
    const float c2c    = -vld * 1.4426950408889634f;            // -ld*log2e
    const float dr     = ex2_(rr * vld * 1.4426950408889634f);  // delta^r
    float zm = fmaxf(fmaxf(zk0, zk1), fmaxf(zk2, zk3));
    float e0 = __expf(zk0 - zm), e1 = __expf(zk1 - zm),
          e2 = __expf(zk2 - zm), e3 = __expf(zk3 - zm);
    const float inv_sum = 1.0f / (e0 + e1 + e2 + e3);
    const float wc0 = e0 * inv_sum * (s0 / (2.f - s0));
    const float wc1 = e1 * inv_sum * (s1 / (2.f - s1));
    const float wc2 = e2 * inv_sum * (s2 / (2.f - s2));
    const float wc3 = e3 * inv_sum * (s3 / (2.f - s3));
    const float nwcx = -(wc0 + wc1 + wc2 + wc3);

    // ---- A at own chunk end: ae = Escan + Q64^(lane+1) * (x0/s) ----
    const float x0 = smr[0];
    const float lf = (float)(lane + 1), lbq = (float)(31 - lane);
    const float g0 = lg2_(P64_0), g1 = lg2_(P64_1), g2 = lg2_(P64_2), g3 = lg2_(P64_3);
    const float ae0 = fmaf(ex2_(lf * g0), x0 * is0, E0);
    const float ae1 = fmaf(ex2_(lf * g1), x0 * is1, E1);
    const float ae2 = fmaf(ex2_(lf * g2), x0 * is2, E2);
    const float ae3 = fmaf(ex2_(lf * g3), x0 * is3, E3);

    // ---- checkpoint conversion: A at i=15/31/47 = eck + q^(i+1) * A[start-1] ----
    float c2p = __shfl_up_sync(ALL, ae2, 1); if (lane == 0) c2p = x0 * is2;
    float c3p = __shfl_up_sync(ALL, ae3, 1); if (lane == 0) c3p = x0 * is3;
    const float ck2_0 = fmaf(C16_2, c2p, eck2_0);
    const float ck2_1 = fmaf(C32_2, c2p, eck2_1);
    const float ck2_2 = fmaf(C48_2, c2p, eck2_2);
    const float ck3_0 = fmaf(C16_3, c3p, eck3_0);
    const float ck3_1 = fmaf(C32_3, c3p, eck3_1);
    const float ck3_2 = fmaf(C48_3, c3p, eck3_2);

    // ---- backward init I = A[T-1] (lane 31's ae), carries cb ----
    const float I0 = __shfl_sync(ALL, ae0, 31);
    const float I1 = __shfl_sync(ALL, ae1, 31);
    const float I2 = __shfl_sync(ALL, ae2, 31);
    const float I3 = __shfl_sync(ALL, ae3, 31);
    float sx0 = __shfl_down_sync(ALL, B0, 1);
    float sx1 = __shfl_down_sync(ALL, B1, 1);
    float sx2 = __shfl_down_sync(ALL, B2, 1);
    float sx3 = __shfl_down_sync(ALL, B3, 1);
    if (lane == 31) { sx0 = 0.f; sx1 = 0.f; sx2 = 0.f; sx3 = 0.f; }
    const float cb0 = fmaf(ex2_(lbq * g0), I0, sx0);
    const float cb1 = fmaf(ex2_(lbq * g1), I1, sx1);
    const float cb2 = fmaf(ex2_(lbq * g2), I2, sx2);
    const float cb3 = fmaf(ex2_(lbq * g3), I3, sx3);

    // ---- final loop (descending): G chain fwd, A inverse with reseeds,
    //      mix + PCEN epilogue, output staged in-place into smem ----
    {
        float gg0 = cb0, gg1 = cb1, gg2 = cb2, gg3 = cb3;
        float a0 = ae0, a1 = ae1;
        float a2 = ae2, a3 = ae3;   // overwritten by reseed at jg=15

#define PCEN_STEP(XI, OO)                                                   \
        {                                                                   \
            const float xi = (XI);                                          \
            gg0 = fmaf(q0, gg0, xi);                                        \
            gg1 = fmaf(q1, gg1, xi);                                        \
            gg2 = fmaf(q2, gg2, xi);                                        \
            gg3 = fmaf(q3, gg3, xi);                                        \
            float M = fmaf(nwcx, xi, 1e-6f);                                \
            M = fmaf(wc0, a0 + gg0, M);                                     \
            M = fmaf(wc1, a1 + gg1, M);                                     \
            M = fmaf(wc2, a2 + gg2, M);                                     \
            M = fmaf(wc3, a3 + gg3, M);                                     \
            float Mp = ex2_(fmaf(nalpha, lg2_(M), c2c));                    \
            float u  = fmaf(xi, Mp, 1.0f);                                  \
            (OO) = fmaf(dr, ex2_(rr * lg2_(u)), -dr);                       \
            a0 = (a0 - xi) * iq0;                                           \
            a1 = (a1 - xi) * iq1;                                           \
            a2 = (a2 - xi) * iq2;                                           \
            a3 = (a3 - xi) * iq3;                                           \
        }

#pragma unroll 4
        for (int jg = 15; jg >= 0; --jg) {
            float4 xv = *reinterpret_cast<const float4*>(smr + wb + jg * 4);
            if ((jg & 3) == 3) {     // reseed unstable inverses every 16 elems
                int sgi = jg >> 2;
                a2 = (sgi == 3) ? ae2 : (sgi == 2) ? ck2_2
                   : (sgi == 1) ? ck2_1 : ck2_0;
                a3 = (sgi == 3) ? ae3 : (sgi == 2) ? ck3_2
                   : (sgi == 1) ? ck3_1 : ck3_0;
            }
            float o0, o1, o2, o3;
            PCEN_STEP(xv.w, o3);
            PCEN_STEP(xv.z, o2);
            PCEN_STEP(xv.y, o1);
            PCEN_STEP(xv.x, o0);
            *reinterpret_cast<float4*>(smr + wb + jg * 4) =
                make_float4(o0, o1, o2, o3);
        }
#undef PCEN_STEP
    }
    __syncwarp();

    // ---- out-copy: padded smem -> coalesced STG.128 ----
    float4* ov = reinterpret_cast<float4*>(out + base);
#pragma unroll
    for (int it = 0; it < 16; ++it) {
        int e = it * 128 + lane * 4;
        float4 v = *reinterpret_cast<const float4*>(smr + SMWORD(e));
        ov[it * 32 + lane] = v;
    }
}

extern "C" void kernel_launch(void* const* d_in, const int* in_sizes, int n_in,
                              void* d_out, int out_size)
{
    const float* x   = (const float*)d_in[0];
    const float* isa = (const float*)d_in[1];
    const float* ldl = (const float*)d_in[2];
    const float* isr = (const float*)d_in[3];
    const float* zks = (const float*)d_in[4];
    float* out = (float*)d_out;

    const int P    = in_sizes[1];                 // 4
    const int F    = in_sizes[4] / (P * 4);       // 128 (z_ks is [P,K,F], K=4)
    const int rows = in_sizes[0] / 2048;          // B*P*F = 8192

    pcen_kernel<<<rows / 4, 128>>>(x, isa, ldl, isr, zks, out, P, F);
}